// round 6
// baseline (speedup 1.0000x reference)
#include <cuda_runtime.h>
#include <cuda_bf16.h>
#include <cfloat>
#include <math.h>
#include <stdint.h>

// ---------------------------------------------------------------------------
// Problem constants
// ---------------------------------------------------------------------------
#define BATCH 16
#define NMAX  1024
#define EMAX  16384
#define DIM   512
// ns = {1024, 820, 656}, ks = {820, 656, 525}

// ---------------------------------------------------------------------------
// Device scratch (static; no cudaMalloc allowed)
// ---------------------------------------------------------------------------
__device__ float d_hb  [BATCH * NMAX * DIM];        // raw gemm outputs (h / x_new)

__device__ float d_xh  [BATCH * NMAX * DIM];        // split of input x (layer 0 A)
__device__ float d_xl  [BATCH * NMAX * DIM];
__device__ float d_xbh [BATCH * NMAX * DIM];        // split pooled features
__device__ float d_xbl [BATCH * NMAX * DIM];
__device__ float d_cath[BATCH * NMAX * 2 * DIM];    // split [agg | x]
__device__ float d_catl[BATCH * NMAX * 2 * DIM];

__device__ float d_wlh [3 * DIM * DIM];             // split c_lin_W
__device__ float d_wll [3 * DIM * DIM];
__device__ float d_wuh [3 * DIM * 2 * DIM];         // split c_upd_W
__device__ float d_wul [3 * DIM * 2 * DIM];

__device__ int   d_srcA[BATCH * EMAX];
__device__ int   d_dstA[BATCH * EMAX];
__device__ int   d_srcB[BATCH * EMAX];
__device__ int   d_dstB[BATCH * EMAX];

__device__ int   d_off [BATCH * (NMAX + 1)];
__device__ int   d_csr [BATCH * EMAX];

__device__ float d_score[BATCH * NMAX];
__device__ int   d_perm [BATCH * NMAX];
__device__ float d_tanhv[BATCH * NMAX];
__device__ int   d_newidx[BATCH * NMAX];

__device__ float d_z[BATCH * 2 * DIM];
__device__ float d_norms[4];

__device__ __forceinline__ const int* esrc(int sel) { return sel ? d_srcB : d_srcA; }
__device__ __forceinline__ const int* edst(int sel) { return sel ? d_dstB : d_dstA; }
__device__ __forceinline__ int* esrc_w(int sel) { return sel ? d_srcB : d_srcA; }
__device__ __forceinline__ int* edst_w(int sel) { return sel ? d_dstB : d_dstA; }

// ---------------------------------------------------------------------------
// tf32 helpers
// ---------------------------------------------------------------------------
__device__ __forceinline__ uint32_t f2tf(float x) {
    uint32_t r;
    asm("cvt.rna.tf32.f32 %0, %1;" : "=r"(r) : "f"(x));
    return r;
}
__device__ __forceinline__ void split2(float v, float& h, float& l) {
    h = __uint_as_float(f2tf(v));
    l = __uint_as_float(f2tf(v - h));
}

__device__ __forceinline__ void mma_tf32(float* c, const uint32_t* a, const uint32_t* b) {
    asm volatile(
        "mma.sync.aligned.m16n8k8.row.col.f32.tf32.tf32.f32 "
        "{%0,%1,%2,%3}, {%4,%5,%6,%7}, {%8,%9}, {%0,%1,%2,%3};"
        : "+f"(c[0]), "+f"(c[1]), "+f"(c[2]), "+f"(c[3])
        : "r"(a[0]), "r"(a[1]), "r"(a[2]), "r"(a[3]), "r"(b[0]), "r"(b[1]));
}

__device__ __forceinline__ void cpasync16(uint32_t dst, const void* src, int szbytes) {
    asm volatile("cp.async.cg.shared.global [%0], [%1], 16, %2;"
                 :: "r"(dst), "l"(src), "r"(szbytes));
}
__device__ __forceinline__ void cpasync_commit() {
    asm volatile("cp.async.commit_group;");
}
template <int N>
__device__ __forceinline__ void cpasync_wait() {
    asm volatile("cp.async.wait_group %0;" :: "n"(N));
}

// ---------------------------------------------------------------------------
// Init / split kernels
// ---------------------------------------------------------------------------
__global__ void init_edges_kernel(const int* __restrict__ ei) {
    int b = blockIdx.y;
    int e = blockIdx.x * blockDim.x + threadIdx.x;
    if (e < EMAX) {
        d_srcA[b * EMAX + e] = ei[(size_t)b * 2 * EMAX + e];
        d_dstA[b * EMAX + e] = ei[(size_t)b * 2 * EMAX + EMAX + e];
    }
}

__global__ void norms_kernel(const float* __restrict__ pw) {
    int l = blockIdx.x;
    int t = threadIdx.x;  // 256
    __shared__ float red[256];
    float s = 0.f;
    for (int j = t; j < DIM; j += 256) {
        float v = pw[l * DIM + j];
        s = fmaf(v, v, s);
    }
    red[t] = s;
    __syncthreads();
    for (int o = 128; o > 0; o >>= 1) {
        if (t < o) red[t] += red[t + o];
        __syncthreads();
    }
    if (t == 0) d_norms[l] = 1.0f / sqrtf(red[0]);
}

// dsel: 0 -> d_xh/d_xl, 1 -> d_wlh/d_wll, 2 -> d_wuh/d_wul
__global__ void split_kernel(const float* __restrict__ src, int dsel, int n) {
    int i = blockIdx.x * blockDim.x + threadIdx.x;
    if (i >= n) return;
    float* H = (dsel == 0) ? d_xh : (dsel == 1) ? d_wlh : d_wuh;
    float* L = (dsel == 0) ? d_xl : (dsel == 1) ? d_wll : d_wul;
    float h, l;
    split2(src[i], h, l);
    H[i] = h;
    L[i] = l;
}

// ---------------------------------------------------------------------------
// 3xTF32 tensor-core GEMM with PRE-SPLIT operands (no cvt in inner loop)
//   C[M,512] = act(A[M,K] @ W[512,K]^T + bias)
//   BM=128, BN=128, BK=8, 256 threads = 8 warps (2x4), warp tile 64x32.
//   Static smem: 4 arrays x 2 stages x 128*PITCH floats = 48 KB exactly.
//   asel: 0 -> A = x-split, 1 -> A = xb-split, 2 -> A = cat-split (K=1024)
//   wsel: 0 -> W = lin-split (K=512),   1 -> W = upd-split (K=1024)
// ---------------------------------------------------------------------------
#define PITCH 12                           // 8 + 4 pad: conflict-free (quad*12+tq)
#define TILE_F (128 * PITCH)               // floats per stage per array

__global__ void __launch_bounds__(256) gemm3t_kernel(
    int asel, int wsel, int layer,
    const float* __restrict__ bias,   // may be nullptr
    int M)
{
    __shared__ float AsH[2][TILE_F];
    __shared__ float AsL[2][TILE_F];
    __shared__ float BsH[2][TILE_F];
    __shared__ float BsL[2][TILE_F];

    const int b = blockIdx.z;
    const int K = (asel == 2) ? (2 * DIM) : DIM;

    const float* Ah =
        (asel == 0) ? (d_xh   + (size_t)b * NMAX * DIM) :
        (asel == 1) ? (d_xbh  + (size_t)b * NMAX * DIM) :
                      (d_cath + (size_t)b * NMAX * 2 * DIM);
    const float* Al =
        (asel == 0) ? (d_xl   + (size_t)b * NMAX * DIM) :
        (asel == 1) ? (d_xbl  + (size_t)b * NMAX * DIM) :
                      (d_catl + (size_t)b * NMAX * 2 * DIM);
    const float* Wh = wsel ? (d_wuh + (size_t)layer * DIM * 2 * DIM)
                           : (d_wlh + (size_t)layer * DIM * DIM);
    const float* Wl = wsel ? (d_wul + (size_t)layer * DIM * 2 * DIM)
                           : (d_wll + (size_t)layer * DIM * DIM);
    float* C = d_hb + (size_t)b * NMAX * DIM;

    const int tid  = threadIdx.x;
    const int brow = blockIdx.y * 128;
    const int bcol = blockIdx.x * 128;

    const int warp = tid >> 5;
    const int lane = tid & 31;
    const int wm   = warp & 1;
    const int wn   = warp >> 1;
    const int quad = lane >> 2;
    const int tq   = lane & 3;

    // gmem->smem: 256 threads, each loads one float4 per array per chunk
    const int lr = tid >> 1;          // 0..127
    const int kq = (tid & 1) * 4;     // 0 / 4
    int arow = brow + lr; if (arow >= M) arow = M - 1;
    const int avalid = (brow + lr) < M ? 16 : 0;
    const float* AhL = Ah + (size_t)arow * K + kq;
    const float* AlL = Al + (size_t)arow * K + kq;
    const float* WhL = Wh + (size_t)(bcol + lr) * K + kq;
    const float* WlL = Wl + (size_t)(bcol + lr) * K + kq;

    const int soff = lr * PITCH + kq;
    uint32_t sAh[2], sAl[2], sBh[2], sBl[2];
#pragma unroll
    for (int st = 0; st < 2; st++) {
        sAh[st] = (uint32_t)__cvta_generic_to_shared(&AsH[st][soff]);
        sAl[st] = (uint32_t)__cvta_generic_to_shared(&AsL[st][soff]);
        sBh[st] = (uint32_t)__cvta_generic_to_shared(&BsH[st][soff]);
        sBl[st] = (uint32_t)__cvta_generic_to_shared(&BsL[st][soff]);
    }

    float acc[4][4][4];
#pragma unroll
    for (int i = 0; i < 4; i++)
#pragma unroll
        for (int j = 0; j < 4; j++)
#pragma unroll
            for (int e = 0; e < 4; e++) acc[i][j][e] = 0.f;

    const int nchunks = K >> 3;

    // prefetch chunk 0 into stage 0
    {
        cpasync16(sAh[0], AhL, avalid);
        cpasync16(sAl[0], AlL, avalid);
        cpasync16(sBh[0], WhL, 16);
        cpasync16(sBl[0], WlL, 16);
        cpasync_commit();
    }

    for (int c = 0; c < nchunks; c++) {
        const int cur = c & 1;
        const int nxt = cur ^ 1;
        if (c + 1 < nchunks) {
            const int k0 = (c + 1) << 3;
            cpasync16(sAh[nxt], AhL + k0, avalid);
            cpasync16(sAl[nxt], AlL + k0, avalid);
            cpasync16(sBh[nxt], WhL + k0, 16);
            cpasync16(sBl[nxt], WlL + k0, 16);
            cpasync_commit();
            cpasync_wait<1>();
        } else {
            cpasync_wait<0>();
        }
        __syncthreads();

        const float* ash = AsH[cur];
        const float* asl = AsL[cur];
        const float* bsh = BsH[cur];
        const float* bsl = BsL[cur];

        uint32_t ahi[4][4], alo[4][4];
#pragma unroll
        for (int mi = 0; mi < 4; mi++) {
            const int r0  = wm * 64 + mi * 16 + quad;
            const int i00 = r0 * PITCH + tq;
            const int i10 = (r0 + 8) * PITCH + tq;
            ahi[mi][0] = __float_as_uint(ash[i00]);
            ahi[mi][1] = __float_as_uint(ash[i10]);
            ahi[mi][2] = __float_as_uint(ash[i00 + 4]);
            ahi[mi][3] = __float_as_uint(ash[i10 + 4]);
            alo[mi][0] = __float_as_uint(asl[i00]);
            alo[mi][1] = __float_as_uint(asl[i10]);
            alo[mi][2] = __float_as_uint(asl[i00 + 4]);
            alo[mi][3] = __float_as_uint(asl[i10 + 4]);
        }
        uint32_t bhi[4][2], blo[4][2];
#pragma unroll
        for (int ni = 0; ni < 4; ni++) {
            const int nr = (wn * 32 + ni * 8 + quad) * PITCH + tq;
            bhi[ni][0] = __float_as_uint(bsh[nr]);
            bhi[ni][1] = __float_as_uint(bsh[nr + 4]);
            blo[ni][0] = __float_as_uint(bsl[nr]);
            blo[ni][1] = __float_as_uint(bsl[nr + 4]);
        }
#pragma unroll
        for (int mi = 0; mi < 4; mi++)
#pragma unroll
            for (int ni = 0; ni < 4; ni++) {
                mma_tf32(acc[mi][ni], alo[mi], bhi[ni]);
                mma_tf32(acc[mi][ni], ahi[mi], blo[ni]);
                mma_tf32(acc[mi][ni], ahi[mi], bhi[ni]);
            }
        __syncthreads();
    }

    // epilogue: bias + relu
#pragma unroll
    for (int mi = 0; mi < 4; mi++) {
        const int r0 = brow + wm * 64 + mi * 16 + quad;
#pragma unroll
        for (int ni = 0; ni < 4; ni++) {
            const int c0 = bcol + wn * 32 + ni * 8 + 2 * tq;
            float bv0 = 0.f, bv1 = 0.f;
            if (bias) { bv0 = bias[c0]; bv1 = bias[c0 + 1]; }
            if (r0 < M) {
                float2 v = make_float2(fmaxf(acc[mi][ni][0] + bv0, 0.f),
                                       fmaxf(acc[mi][ni][1] + bv1, 0.f));
                *(float2*)(C + (size_t)r0 * DIM + c0) = v;
            }
            if (r0 + 8 < M) {
                float2 v = make_float2(fmaxf(acc[mi][ni][2] + bv0, 0.f),
                                       fmaxf(acc[mi][ni][3] + bv1, 0.f));
                *(float2*)(C + (size_t)(r0 + 8) * DIM + c0) = v;
            }
        }
    }
}

// ---------------------------------------------------------------------------
// Fused CSR build: one block per batch
// ---------------------------------------------------------------------------
__global__ void __launch_bounds__(1024) build_csr_kernel(int sel) {
    __shared__ int sh[NMAX];
    __shared__ int cur[NMAX];
    const int b = blockIdx.x, t = threadIdx.x;

    sh[t] = 0;
    __syncthreads();

    const int* S = esrc(sel) + b * EMAX;
    const int* D = edst(sel) + b * EMAX;

#pragma unroll 4
    for (int e = t; e < EMAX; e += 1024) {
        int s = S[e], d = D[e];
        if (s >= 0 && s != d) atomicAdd(&sh[d], 1);
    }
    __syncthreads();

    int v = sh[t];
    for (int off = 1; off < NMAX; off <<= 1) {
        int add = (t >= off) ? sh[t - off] : 0;
        __syncthreads();
        sh[t] += add;
        __syncthreads();
    }
    int excl = sh[t] - v;
    d_off[b * (NMAX + 1) + t] = excl;
    cur[t] = excl;
    if (t == NMAX - 1) d_off[b * (NMAX + 1) + NMAX] = sh[t];
    __syncthreads();

#pragma unroll 4
    for (int e = t; e < EMAX; e += 1024) {
        int s = S[e], d = D[e];
        if (s >= 0 && s != d) {
            int pos = atomicAdd(&cur[d], 1);
            d_csr[b * EMAX + pos] = s;
        }
    }
}

// ---------------------------------------------------------------------------
// Aggregation + concat, writing SPLIT cat:
//   cat[i,:512] = h[i] + sum_{j->i} h[j];  cat[i,512:] = x[i] (pass-through split)
// xsel: 0 -> x-split from d_xh/d_xl, 1 -> from d_xbh/d_xbl
// ---------------------------------------------------------------------------
__global__ void __launch_bounds__(128) agg_cat_kernel(int xsel, int n) {
    int b = blockIdx.y, i = blockIdx.x;
    if (i >= n) return;
    int t = threadIdx.x;
    size_t row = (size_t)(b * NMAX + i);
    const float* xsh = (xsel ? d_xbh : d_xh) + row * DIM;
    const float* xsl = (xsel ? d_xbl : d_xl) + row * DIM;

    float4 acc = ((const float4*)(d_hb + row * DIM))[t];
    int beg = d_off[b * (NMAX + 1) + i];
    int end = d_off[b * (NMAX + 1) + i + 1];
    for (int e = beg; e < end; e++) {
        int s = d_csr[b * EMAX + e];
        float4 v = ((const float4*)(d_hb + (size_t)(b * NMAX + s) * DIM))[t];
        acc.x += v.x; acc.y += v.y; acc.z += v.z; acc.w += v.w;
    }
    float4 hh, ll;
    split2(acc.x, hh.x, ll.x);
    split2(acc.y, hh.y, ll.y);
    split2(acc.z, hh.z, ll.z);
    split2(acc.w, hh.w, ll.w);
    ((float4*)(d_cath + row * 2 * DIM))[t] = hh;
    ((float4*)(d_catl + row * 2 * DIM))[t] = ll;
    ((float4*)(d_cath + row * 2 * DIM))[128 + t] = ((const float4*)xsh)[t];
    ((float4*)(d_catl + row * 2 * DIM))[128 + t] = ((const float4*)xsl)[t];
}

// ---------------------------------------------------------------------------
// Scores: score[i] = (x_new[i] . w) / ||w||    (x_new raw in d_hb)
// ---------------------------------------------------------------------------
__global__ void score_kernel(const float* __restrict__ pw, int layer, int n) {
    int b    = blockIdx.y;
    int node = blockIdx.x * 8 + (threadIdx.x >> 5);
    int lane = threadIdx.x & 31;
    if (node >= n) return;
    const float* row = d_hb + (size_t)(b * NMAX + node) * DIM;
    const float* w   = pw + layer * DIM;
    float s = 0.f;
#pragma unroll 4
    for (int j = lane; j < DIM; j += 32) s = fmaf(row[j], w[j], s);
#pragma unroll
    for (int o = 16; o > 0; o >>= 1) s += __shfl_xor_sync(0xffffffffu, s, o);
    if (lane == 0) d_score[b * NMAX + node] = s * d_norms[layer];
}

// ---------------------------------------------------------------------------
// Top-k via bitonic sort (tie-break: lower index wins)
// ---------------------------------------------------------------------------
__global__ void __launch_bounds__(512) topk_kernel(int n, int k) {
    __shared__ float sv[NMAX];
    __shared__ int   si[NMAX];
    int b = blockIdx.x, t = threadIdx.x;

    for (int i = t; i < NMAX; i += 512) {
        sv[i] = (i < n) ? d_score[b * NMAX + i] : -FLT_MAX;
        si[i] = i;
    }
    __syncthreads();

    for (int size = 2; size <= NMAX; size <<= 1) {
        for (int stride = size >> 1; stride > 0; stride >>= 1) {
            for (int i = t; i < NMAX; i += 512) {
                int j = i ^ stride;
                if (j > i) {
                    float v1 = sv[i], v2 = sv[j];
                    int   i1 = si[i], i2 = si[j];
                    bool gt = (v1 > v2) || (v1 == v2 && i1 < i2);
                    bool up = ((i & size) == 0);
                    if (up ? gt : !gt) {
                        sv[i] = v2; sv[j] = v1;
                        si[i] = i2; si[j] = i1;
                    }
                }
            }
            __syncthreads();
        }
    }

    for (int i = t; i < NMAX; i += 512) d_newidx[b * NMAX + i] = -1;
    __syncthreads();
    for (int j = t; j < k; j += 512) {
        int   src = si[NMAX - 1 - j];
        float val = sv[NMAX - 1 - j];
        d_perm [b * NMAX + j]    = src;
        d_tanhv[b * NMAX + j]    = tanhf(val);
        d_newidx[b * NMAX + src] = j;
    }
}

// ---------------------------------------------------------------------------
// Gather pooled nodes: xb_split[j] = split(hb[perm[j]] * tanh(val[j]))
// ---------------------------------------------------------------------------
__global__ void __launch_bounds__(128) gather_kernel(int k) {
    int b = blockIdx.y, j = blockIdx.x;
    if (j >= k) return;
    int t = threadIdx.x;
    int   p  = d_perm [b * NMAX + j];
    float tv = d_tanhv[b * NMAX + j];
    float4 v = ((const float4*)(d_hb + (size_t)(b * NMAX + p) * DIM))[t];
    v.x *= tv; v.y *= tv; v.z *= tv; v.w *= tv;
    float4 hh, ll;
    split2(v.x, hh.x, ll.x);
    split2(v.y, hh.y, ll.y);
    split2(v.z, hh.z, ll.z);
    split2(v.w, hh.w, ll.w);
    ((float4*)(d_xbh + (size_t)(b * NMAX + j) * DIM))[t] = hh;
    ((float4*)(d_xbl + (size_t)(b * NMAX + j) * DIM))[t] = ll;
}

// ---------------------------------------------------------------------------
// Remap edges into pooled index space
// ---------------------------------------------------------------------------
__global__ void remap_kernel(int inSel, int outSel) {
    int b = blockIdx.y;
    int e = blockIdx.x * blockDim.x + threadIdx.x;
    if (e >= EMAX) return;
    int s = esrc(inSel)[b * EMAX + e];
    int d = edst(inSel)[b * EMAX + e];
    int s2 = -1, d2 = 0;
    if (s >= 0) {
        s2 = d_newidx[b * NMAX + s];
        d2 = d_newidx[b * NMAX + d];
        if (d2 < 0) s2 = -1;
        if (d2 < 0) d2 = 0;
    }
    esrc_w(outSel)[b * EMAX + e] = s2;
    edst_w(outSel)[b * EMAX + e] = (s2 >= 0) ? d2 : 0;
}

// ---------------------------------------------------------------------------
// Readout over split pooled features: v = hi + lo
// ---------------------------------------------------------------------------
__global__ void readout_kernel(int k, int first) {
    int b = blockIdx.y;
    int f = blockIdx.x * 256 + threadIdx.x;
    const float* bh = d_xbh + (size_t)b * NMAX * DIM + f;
    const float* bl = d_xbl + (size_t)b * NMAX * DIM + f;
    float mx = -FLT_MAX, sm = 0.f;
#pragma unroll 4
    for (int j = 0; j < k; j++) {
        float v = bh[(size_t)j * DIM] + bl[(size_t)j * DIM];
        mx = fmaxf(mx, v);
        sm += v;
    }
    float mean = sm / (float)k;
    if (first) {
        d_z[b * 2 * DIM + f]       = mx;
        d_z[b * 2 * DIM + DIM + f] = mean;
    } else {
        d_z[b * 2 * DIM + f]       += mx;
        d_z[b * 2 * DIM + DIM + f] += mean;
    }
}

// ---------------------------------------------------------------------------
// Final MLP: out = relu(z @ lin1^T + b1) @ lin2^T + b2
// ---------------------------------------------------------------------------
__global__ void __launch_bounds__(256) mlp_kernel(
    const float* __restrict__ lin1W, const float* __restrict__ lin1b,
    const float* __restrict__ lin2W, const float* __restrict__ lin2b,
    float* __restrict__ out)
{
    int b = blockIdx.x, t = threadIdx.x;
    int warp = t >> 5, lane = t & 31;
    __shared__ float zsh[2 * DIM];
    __shared__ float y1[DIM];

    for (int i = t; i < 2 * DIM; i += 256) zsh[i] = d_z[b * 2 * DIM + i];
    __syncthreads();

    for (int o = warp * 64; o < warp * 64 + 64; o++) {
        const float* wr = lin1W + (size_t)o * 2 * DIM;
        float s = 0.f;
        for (int j = lane; j < 2 * DIM; j += 32) s = fmaf(zsh[j], wr[j], s);
#pragma unroll
        for (int off = 16; off > 0; off >>= 1) s += __shfl_xor_sync(0xffffffffu, s, off);
        if (lane == 0) y1[o] = fmaxf(s + lin1b[o], 0.f);
    }
    __syncthreads();

    for (int o = warp * 32; o < warp * 32 + 32; o++) {
        const float* wr = lin2W + (size_t)o * DIM;
        float s = 0.f;
        for (int j = lane; j < DIM; j += 32) s = fmaf(y1[j], wr[j], s);
#pragma unroll
        for (int off = 16; off > 0; off >>= 1) s += __shfl_xor_sync(0xffffffffu, s, off);
        if (lane == 0) out[b * 256 + o] = s + lin2b[o];
    }
}

// ---------------------------------------------------------------------------
// Host launcher — kernel launches ONLY (graph-capture safe, no runtime API)
// ---------------------------------------------------------------------------
extern "C" void kernel_launch(void* const* d_in, const int* in_sizes, int n_in,
                              void* d_out, int out_size)
{
    const float* x       = (const float*)d_in[0];
    const int*   ei      = (const int*)  d_in[1];
    const float* c_lin_W = (const float*)d_in[2];
    const float* c_lin_b = (const float*)d_in[3];
    const float* c_upd_W = (const float*)d_in[4];
    const float* pool_w  = (const float*)d_in[5];
    const float* lin1_W  = (const float*)d_in[6];
    const float* lin1_b  = (const float*)d_in[7];
    const float* lin2_W  = (const float*)d_in[8];
    const float* lin2_b  = (const float*)d_in[9];
    float* out = (float*)d_out;

    const int ns[3] = {1024, 820, 656};
    const int ks[3] = {820, 656, 525};

    init_edges_kernel<<<dim3(EMAX / 256, BATCH), 256>>>(ei);
    norms_kernel<<<3, 256>>>(pool_w);

    // pre-split input x and both weight banks into tf32 hi/lo
    {
        int nx = BATCH * NMAX * DIM;
        split_kernel<<<(nx + 255) / 256, 256>>>(x, 0, nx);
        int nl = 3 * DIM * DIM;
        split_kernel<<<(nl + 255) / 256, 256>>>(c_lin_W, 1, nl);
        int nu = 3 * DIM * 2 * DIM;
        split_kernel<<<(nu + 255) / 256, 256>>>(c_upd_W, 2, nu);
    }

    for (int l = 0; l < 3; l++) {
        int n = ns[l], k = ks[l];
        int inSel = l & 1;
        int outSel = inSel ^ 1;
        int xsel = (l == 0) ? 0 : 1;

        // h = relu(x @ Wl^T + bl)
        gemm3t_kernel<<<dim3(DIM / 128, (n + 127) / 128, BATCH), 256>>>(
            xsel, 0, l, c_lin_b + l * DIM, n);

        build_csr_kernel<<<BATCH, 1024>>>(inSel);

        agg_cat_kernel<<<dim3(n, BATCH), 128>>>(xsel, n);

        // x_new = relu(cat @ Wu^T)
        gemm3t_kernel<<<dim3(DIM / 128, (n + 127) / 128, BATCH), 256>>>(
            2, 1, l, nullptr, n);

        score_kernel<<<dim3((n + 7) / 8, BATCH), 256>>>(pool_w, l, n);
        topk_kernel<<<BATCH, 512>>>(n, k);
        gather_kernel<<<dim3(k, BATCH), 128>>>(k);
        if (l < 2)
            remap_kernel<<<dim3(EMAX / 256, BATCH), 256>>>(inSel, outSel);

        readout_kernel<<<dim3(DIM / 256, BATCH), 256>>>(k, l == 0 ? 1 : 0);
    }

    mlp_kernel<<<BATCH, 256>>>(lin1_W, lin1_b, lin2_W, lin2_b, out);
}

// round 9
// speedup vs baseline: 1.7168x; 1.7168x over previous
#include <cuda_runtime.h>
#include <cuda_fp16.h>
#include <cfloat>
#include <math.h>
#include <stdint.h>

// ---------------------------------------------------------------------------
// Problem constants
// ---------------------------------------------------------------------------
#define BATCH 16
#define NMAX  1024
#define EMAX  16384
#define DIM   512
// ns = {1024, 820, 656}, ks = {820, 656, 525}

// ---------------------------------------------------------------------------
// Device scratch (static; no cudaMalloc allowed)
// ---------------------------------------------------------------------------
__device__ float d_hb [BATCH * NMAX * DIM];     // raw gemm outputs (h / x_new)
__device__ float d_xbf[BATCH * NMAX * DIM];     // pooled features fp32 (readout)

// fp16 hi/lo operand planes (row-major, K contiguous)
__device__ __half d_x0h[BATCH * NMAX * DIM];    // input x split
__device__ __half d_x0l[BATCH * NMAX * DIM];
__device__ __half d_xbh[BATCH * NMAX * DIM];    // pooled split
__device__ __half d_xbl[BATCH * NMAX * DIM];
__device__ __half d_cath[BATCH * NMAX * 2 * DIM]; // [agg | x] split
__device__ __half d_catl[BATCH * NMAX * 2 * DIM];

__device__ __half d_wlh[3 * DIM * DIM];         // c_lin_W split
__device__ __half d_wll[3 * DIM * DIM];
__device__ __half d_wuh[3 * DIM * 2 * DIM];     // c_upd_W split
__device__ __half d_wul[3 * DIM * 2 * DIM];

__device__ int   d_srcA[BATCH * EMAX];
__device__ int   d_dstA[BATCH * EMAX];
__device__ int   d_srcB[BATCH * EMAX];
__device__ int   d_dstB[BATCH * EMAX];

__device__ int   d_off [BATCH * (NMAX + 1)];
__device__ int   d_csr [BATCH * EMAX];

__device__ float d_score[BATCH * NMAX];
__device__ int   d_perm [BATCH * NMAX];
__device__ float d_tanhv[BATCH * NMAX];
__device__ int   d_newidx[BATCH * NMAX];

__device__ float d_z[BATCH * 2 * DIM];
__device__ float d_norms[4];

__device__ __forceinline__ const int* esrc(int sel) { return sel ? d_srcB : d_srcA; }
__device__ __forceinline__ const int* edst(int sel) { return sel ? d_dstB : d_dstA; }
__device__ __forceinline__ int* esrc_w(int sel) { return sel ? d_srcB : d_srcA; }
__device__ __forceinline__ int* edst_w(int sel) { return sel ? d_dstB : d_dstA; }

// ---------------------------------------------------------------------------
// fp16 helpers
// ---------------------------------------------------------------------------
__device__ __forceinline__ void split4h(float4 v, uint2& h, uint2& l) {
    __half hx = __float2half(v.x), hy = __float2half(v.y);
    __half hz = __float2half(v.z), hw = __float2half(v.w);
    __half lx = __float2half(v.x - __half2float(hx));
    __half ly = __float2half(v.y - __half2float(hy));
    __half lz = __float2half(v.z - __half2float(hz));
    __half lw = __float2half(v.w - __half2float(hw));
    h.x = ((uint32_t)__half_as_ushort(hy) << 16) | __half_as_ushort(hx);
    h.y = ((uint32_t)__half_as_ushort(hw) << 16) | __half_as_ushort(hz);
    l.x = ((uint32_t)__half_as_ushort(ly) << 16) | __half_as_ushort(lx);
    l.y = ((uint32_t)__half_as_ushort(lw) << 16) | __half_as_ushort(lz);
}

__device__ __forceinline__ void mma_h16(float* c, const uint32_t* a, const uint32_t* b) {
    asm volatile(
        "mma.sync.aligned.m16n8k16.row.col.f32.f16.f16.f32 "
        "{%0,%1,%2,%3}, {%4,%5,%6,%7}, {%8,%9}, {%0,%1,%2,%3};"
        : "+f"(c[0]), "+f"(c[1]), "+f"(c[2]), "+f"(c[3])
        : "r"(a[0]), "r"(a[1]), "r"(a[2]), "r"(a[3]), "r"(b[0]), "r"(b[1]));
}

__device__ __forceinline__ void cpasync16(uint32_t dst, const void* src, int szbytes) {
    asm volatile("cp.async.cg.shared.global [%0], [%1], 16, %2;"
                 :: "r"(dst), "l"(src), "r"(szbytes));
}
__device__ __forceinline__ void cpasync_commit() {
    asm volatile("cp.async.commit_group;");
}
template <int N>
__device__ __forceinline__ void cpasync_wait() {
    asm volatile("cp.async.wait_group %0;" :: "n"(N));
}

// ---------------------------------------------------------------------------
// Init / split kernels
// ---------------------------------------------------------------------------
__global__ void init_edges_kernel(const int* __restrict__ ei) {
    int b = blockIdx.y;
    int e = blockIdx.x * blockDim.x + threadIdx.x;
    if (e < EMAX) {
        d_srcA[b * EMAX + e] = ei[(size_t)b * 2 * EMAX + e];
        d_dstA[b * EMAX + e] = ei[(size_t)b * 2 * EMAX + EMAX + e];
    }
}

__global__ void norms_kernel(const float* __restrict__ pw) {
    int l = blockIdx.x;
    int t = threadIdx.x;
    __shared__ float red[256];
    float s = 0.f;
    for (int j = t; j < DIM; j += 256) {
        float v = pw[l * DIM + j];
        s = fmaf(v, v, s);
    }
    red[t] = s;
    __syncthreads();
    for (int o = 128; o > 0; o >>= 1) {
        if (t < o) red[t] += red[t + o];
        __syncthreads();
    }
    if (t == 0) d_norms[l] = 1.0f / sqrtf(red[0]);
}

// dsel: 0 -> x0, 1 -> wl, 2 -> wu   (flat elementwise, float4 granules)
__global__ void split_kernel(const float* __restrict__ src, int dsel, int n4) {
    int i = blockIdx.x * blockDim.x + threadIdx.x;   // granule index (4 floats)
    if (i >= n4) return;
    __half* H = (dsel == 0) ? d_x0h : (dsel == 1) ? d_wlh : d_wuh;
    __half* L = (dsel == 0) ? d_x0l : (dsel == 1) ? d_wll : d_wul;
    float4 v = ((const float4*)src)[i];
    uint2 h, l;
    split4h(v, h, l);
    ((uint2*)H)[i] = h;
    ((uint2*)L)[i] = l;
}

// ---------------------------------------------------------------------------
// 3xFP16 tensor-core GEMM with pre-split operands
//   C[M,512] = act(A[M,K] @ W[512,K]^T + bias)
//   BM=128, BN=128, BK=16, 256 threads = 8 warps (2x4), warp tile 64x32.
//   Static smem: 4 arrays x 2 stages x 128*PITCH_H halves = 48 KB exactly.
//   asel: 0 -> A = x0 planes, 1 -> A = xb planes, 2 -> A = cat planes (K=1024)
// ---------------------------------------------------------------------------
#define PITCH_H 24                         // halves: 16 data + 8 pad (12 words)
#define TILE_H (128 * PITCH_H)

__global__ void __launch_bounds__(256) gemm_h3_kernel(
    int asel, int layer,
    const float* __restrict__ bias,   // may be nullptr
    int M)
{
    __shared__ __half AsH[2][TILE_H];
    __shared__ __half AsL[2][TILE_H];
    __shared__ __half BsH[2][TILE_H];
    __shared__ __half BsL[2][TILE_H];

    const int b = blockIdx.z;
    const int K = (asel == 2) ? (2 * DIM) : DIM;

    const __half* Ah =
        (asel == 0) ? (d_x0h  + (size_t)b * NMAX * DIM) :
        (asel == 1) ? (d_xbh  + (size_t)b * NMAX * DIM) :
                      (d_cath + (size_t)b * NMAX * 2 * DIM);
    const __half* Al =
        (asel == 0) ? (d_x0l  + (size_t)b * NMAX * DIM) :
        (asel == 1) ? (d_xbl  + (size_t)b * NMAX * DIM) :
                      (d_catl + (size_t)b * NMAX * 2 * DIM);
    const __half* Wh = (asel == 2) ? (d_wuh + (size_t)layer * DIM * 2 * DIM)
                                   : (d_wlh + (size_t)layer * DIM * DIM);
    const __half* Wl = (asel == 2) ? (d_wul + (size_t)layer * DIM * 2 * DIM)
                                   : (d_wll + (size_t)layer * DIM * DIM);
    float* C = d_hb + (size_t)b * NMAX * DIM;

    const int tid  = threadIdx.x;
    const int brow = blockIdx.y * 128;
    const int bcol = blockIdx.x * 128;

    const int warp = tid >> 5;
    const int lane = tid & 31;
    const int wm   = warp & 1;    // 0..1  (64 rows each)
    const int wn   = warp >> 1;   // 0..3  (32 cols each)
    const int quad = lane >> 2;   // 0..7
    const int tq   = lane & 3;    // 0..3

    // gmem->smem: thread covers row lr, half hh (8 halves = 16 bytes)
    const int lr = tid >> 1;
    const int hh = (tid & 1) * 8;
    int arow = brow + lr; if (arow >= M) arow = M - 1;
    const int avalid = (brow + lr) < M ? 16 : 0;
    const __half* AhL = Ah + (size_t)arow * K + hh;
    const __half* AlL = Al + (size_t)arow * K + hh;
    const __half* WhL = Wh + (size_t)(bcol + lr) * K + hh;
    const __half* WlL = Wl + (size_t)(bcol + lr) * K + hh;

    const int soff = lr * PITCH_H + hh;
    uint32_t sAh[2], sAl[2], sBh[2], sBl[2];
#pragma unroll
    for (int st = 0; st < 2; st++) {
        sAh[st] = (uint32_t)__cvta_generic_to_shared(&AsH[st][soff]);
        sAl[st] = (uint32_t)__cvta_generic_to_shared(&AsL[st][soff]);
        sBh[st] = (uint32_t)__cvta_generic_to_shared(&BsH[st][soff]);
        sBl[st] = (uint32_t)__cvta_generic_to_shared(&BsL[st][soff]);
    }

    float acc[4][4][4];
#pragma unroll
    for (int i = 0; i < 4; i++)
#pragma unroll
        for (int j = 0; j < 4; j++)
#pragma unroll
            for (int e = 0; e < 4; e++) acc[i][j][e] = 0.f;

    const int nchunks = K >> 4;

    // prefetch chunk 0 into stage 0
    {
        cpasync16(sAh[0], AhL, avalid);
        cpasync16(sAl[0], AlL, avalid);
        cpasync16(sBh[0], WhL, 16);
        cpasync16(sBl[0], WlL, 16);
        cpasync_commit();
    }

    for (int c = 0; c < nchunks; c++) {
        const int cur = c & 1;
        const int nxt = cur ^ 1;
        if (c + 1 < nchunks) {
            const int k0 = (c + 1) << 4;
            cpasync16(sAh[nxt], AhL + k0, avalid);
            cpasync16(sAl[nxt], AlL + k0, avalid);
            cpasync16(sBh[nxt], WhL + k0, 16);
            cpasync16(sBl[nxt], WlL + k0, 16);
            cpasync_commit();
            cpasync_wait<1>();
        } else {
            cpasync_wait<0>();
        }
        __syncthreads();

        const __half* ash = AsH[cur];
        const __half* asl = AsL[cur];
        const __half* bsh = BsH[cur];
        const __half* bsl = BsL[cur];

        uint32_t ah[4][4], al[4][4];
#pragma unroll
        for (int mi = 0; mi < 4; mi++) {
            const int r0 = wm * 64 + mi * 16 + quad;
            const __half* p0 = ash + r0 * PITCH_H + tq * 2;
            const __half* p1 = ash + (r0 + 8) * PITCH_H + tq * 2;
            const __half* q0 = asl + r0 * PITCH_H + tq * 2;
            const __half* q1 = asl + (r0 + 8) * PITCH_H + tq * 2;
            ah[mi][0] = *(const uint32_t*)p0;
            ah[mi][1] = *(const uint32_t*)p1;
            ah[mi][2] = *(const uint32_t*)(p0 + 8);
            ah[mi][3] = *(const uint32_t*)(p1 + 8);
            al[mi][0] = *(const uint32_t*)q0;
            al[mi][1] = *(const uint32_t*)q1;
            al[mi][2] = *(const uint32_t*)(q0 + 8);
            al[mi][3] = *(const uint32_t*)(q1 + 8);
        }
        uint32_t bh[4][2], bl[4][2];
#pragma unroll
        for (int ni = 0; ni < 4; ni++) {
            const int nr = wn * 32 + ni * 8 + quad;
            const __half* pb = bsh + nr * PITCH_H + tq * 2;
            const __half* qb = bsl + nr * PITCH_H + tq * 2;
            bh[ni][0] = *(const uint32_t*)pb;
            bh[ni][1] = *(const uint32_t*)(pb + 8);
            bl[ni][0] = *(const uint32_t*)qb;
            bl[ni][1] = *(const uint32_t*)(qb + 8);
        }
#pragma unroll
        for (int mi = 0; mi < 4; mi++)
#pragma unroll
            for (int ni = 0; ni < 4; ni++) {
                mma_h16(acc[mi][ni], al[mi], bh[ni]);
                mma_h16(acc[mi][ni], ah[mi], bl[ni]);
                mma_h16(acc[mi][ni], ah[mi], bh[ni]);
            }
        __syncthreads();
    }

    // epilogue: bias + relu
#pragma unroll
    for (int mi = 0; mi < 4; mi++) {
        const int r0 = brow + wm * 64 + mi * 16 + quad;
#pragma unroll
        for (int ni = 0; ni < 4; ni++) {
            const int c0 = bcol + wn * 32 + ni * 8 + 2 * tq;
            float bv0 = 0.f, bv1 = 0.f;
            if (bias) { bv0 = bias[c0]; bv1 = bias[c0 + 1]; }
            if (r0 < M) {
                float2 v = make_float2(fmaxf(acc[mi][ni][0] + bv0, 0.f),
                                       fmaxf(acc[mi][ni][1] + bv1, 0.f));
                *(float2*)(C + (size_t)r0 * DIM + c0) = v;
            }
            if (r0 + 8 < M) {
                float2 v = make_float2(fmaxf(acc[mi][ni][2] + bv0, 0.f),
                                       fmaxf(acc[mi][ni][3] + bv1, 0.f));
                *(float2*)(C + (size_t)(r0 + 8) * DIM + c0) = v;
            }
        }
    }
}

// ---------------------------------------------------------------------------
// Fused CSR build
// ---------------------------------------------------------------------------
__global__ void __launch_bounds__(1024) build_csr_kernel(int sel) {
    __shared__ int sh[NMAX];
    __shared__ int cur[NMAX];
    const int b = blockIdx.x, t = threadIdx.x;

    sh[t] = 0;
    __syncthreads();

    const int* S = esrc(sel) + b * EMAX;
    const int* D = edst(sel) + b * EMAX;

#pragma unroll 4
    for (int e = t; e < EMAX; e += 1024) {
        int s = S[e], d = D[e];
        if (s >= 0 && s != d) atomicAdd(&sh[d], 1);
    }
    __syncthreads();

    int v = sh[t];
    for (int off = 1; off < NMAX; off <<= 1) {
        int add = (t >= off) ? sh[t - off] : 0;
        __syncthreads();
        sh[t] += add;
        __syncthreads();
    }
    int excl = sh[t] - v;
    d_off[b * (NMAX + 1) + t] = excl;
    cur[t] = excl;
    if (t == NMAX - 1) d_off[b * (NMAX + 1) + NMAX] = sh[t];
    __syncthreads();

#pragma unroll 4
    for (int e = t; e < EMAX; e += 1024) {
        int s = S[e], d = D[e];
        if (s >= 0 && s != d) {
            int pos = atomicAdd(&cur[d], 1);
            d_csr[b * EMAX + pos] = s;
        }
    }
}

// ---------------------------------------------------------------------------
// Aggregation + concat, split to fp16:
//   cat[i,:512] = split(h[i] + sum_{j->i} h[j]);  cat[i,512:] = x-split copy
// xsel: 0 -> copy from x0 planes, 1 -> from xb planes
// ---------------------------------------------------------------------------
__global__ void __launch_bounds__(128) agg_cat_kernel(int xsel, int n) {
    int b = blockIdx.y, i = blockIdx.x;
    if (i >= n) return;
    int t = threadIdx.x;
    size_t row = (size_t)(b * NMAX + i);
    const __half* xsh = (xsel ? d_xbh : d_x0h) + row * DIM;
    const __half* xsl = (xsel ? d_xbl : d_x0l) + row * DIM;

    float4 acc = ((const float4*)(d_hb + row * DIM))[t];
    int beg = d_off[b * (NMAX + 1) + i];
    int end = d_off[b * (NMAX + 1) + i + 1];
    for (int e = beg; e < end; e++) {
        int s = d_csr[b * EMAX + e];
        float4 v = ((const float4*)(d_hb + (size_t)(b * NMAX + s) * DIM))[t];
        acc.x += v.x; acc.y += v.y; acc.z += v.z; acc.w += v.w;
    }
    uint2 h, l;
    split4h(acc, h, l);
    __half* ch = d_cath + row * 2 * DIM;
    __half* cl = d_catl + row * 2 * DIM;
    ((uint2*)(ch))[t] = h;                      // cols 4t..4t+3
    ((uint2*)(cl))[t] = l;
    ((uint2*)(ch + DIM))[t] = ((const uint2*)xsh)[t];   // cols 512+4t..
    ((uint2*)(cl + DIM))[t] = ((const uint2*)xsl)[t];
}

// ---------------------------------------------------------------------------
// Scores: score[i] = (x_new[i] . w) / ||w||    (from fp32 d_hb)
// ---------------------------------------------------------------------------
__global__ void score_kernel(const float* __restrict__ pw, int layer, int n) {
    int b    = blockIdx.y;
    int node = blockIdx.x * 8 + (threadIdx.x >> 5);
    int lane = threadIdx.x & 31;
    if (node >= n) return;
    const float* row = d_hb + (size_t)(b * NMAX + node) * DIM;
    const float* w   = pw + layer * DIM;
    float s = 0.f;
#pragma unroll 4
    for (int j = lane; j < DIM; j += 32) s = fmaf(row[j], w[j], s);
#pragma unroll
    for (int o = 16; o > 0; o >>= 1) s += __shfl_xor_sync(0xffffffffu, s, o);
    if (lane == 0) d_score[b * NMAX + node] = s * d_norms[layer];
}

// ---------------------------------------------------------------------------
// Top-k via bitonic sort (tie-break: lower index wins)
// ---------------------------------------------------------------------------
__global__ void __launch_bounds__(512) topk_kernel(int n, int k) {
    __shared__ float sv[NMAX];
    __shared__ int   si[NMAX];
    int b = blockIdx.x, t = threadIdx.x;

    for (int i = t; i < NMAX; i += 512) {
        sv[i] = (i < n) ? d_score[b * NMAX + i] : -FLT_MAX;
        si[i] = i;
    }
    __syncthreads();

    for (int size = 2; size <= NMAX; size <<= 1) {
        for (int stride = size >> 1; stride > 0; stride >>= 1) {
            for (int i = t; i < NMAX; i += 512) {
                int j = i ^ stride;
                if (j > i) {
                    float v1 = sv[i], v2 = sv[j];
                    int   i1 = si[i], i2 = si[j];
                    bool gt = (v1 > v2) || (v1 == v2 && i1 < i2);
                    bool up = ((i & size) == 0);
                    if (up ? gt : !gt) {
                        sv[i] = v2; sv[j] = v1;
                        si[i] = i2; si[j] = i1;
                    }
                }
            }
            __syncthreads();
        }
    }

    for (int i = t; i < NMAX; i += 512) d_newidx[b * NMAX + i] = -1;
    __syncthreads();
    for (int j = t; j < k; j += 512) {
        int   src = si[NMAX - 1 - j];
        float val = sv[NMAX - 1 - j];
        d_perm [b * NMAX + j]    = src;
        d_tanhv[b * NMAX + j]    = tanhf(val);
        d_newidx[b * NMAX + src] = j;
    }
}

// ---------------------------------------------------------------------------
// Gather: xb = hb[perm]*tanh -> fp32 (readout) + fp16 hi/lo planes (GEMM A)
// ---------------------------------------------------------------------------
__global__ void __launch_bounds__(128) gather_kernel(int k) {
    int b = blockIdx.y, j = blockIdx.x;
    if (j >= k) return;
    int t = threadIdx.x;
    int   p  = d_perm [b * NMAX + j];
    float tv = d_tanhv[b * NMAX + j];
    float4 v = ((const float4*)(d_hb + (size_t)(b * NMAX + p) * DIM))[t];
    v.x *= tv; v.y *= tv; v.z *= tv; v.w *= tv;
    ((float4*)(d_xbf + (size_t)(b * NMAX + j) * DIM))[t] = v;
    uint2 h, l;
    split4h(v, h, l);
    ((uint2*)(d_xbh + (size_t)(b * NMAX + j) * DIM))[t] = h;
    ((uint2*)(d_xbl + (size_t)(b * NMAX + j) * DIM))[t] = l;
}

// ---------------------------------------------------------------------------
// Remap edges into pooled index space
// ---------------------------------------------------------------------------
__global__ void remap_kernel(int inSel, int outSel) {
    int b = blockIdx.y;
    int e = blockIdx.x * blockDim.x + threadIdx.x;
    if (e >= EMAX) return;
    int s = esrc(inSel)[b * EMAX + e];
    int d = edst(inSel)[b * EMAX + e];
    int s2 = -1, d2 = 0;
    if (s >= 0) {
        s2 = d_newidx[b * NMAX + s];
        d2 = d_newidx[b * NMAX + d];
        if (d2 < 0) s2 = -1;
        if (d2 < 0) d2 = 0;
    }
    esrc_w(outSel)[b * EMAX + e] = s2;
    edst_w(outSel)[b * EMAX + e] = (s2 >= 0) ? d2 : 0;
}

// ---------------------------------------------------------------------------
// Readout (reads fp32 d_xbf)
// ---------------------------------------------------------------------------
__global__ void readout_kernel(int k, int first) {
    int b = blockIdx.y;
    int f = blockIdx.x * 256 + threadIdx.x;
    const float* base = d_xbf + (size_t)b * NMAX * DIM + f;
    float mx = -FLT_MAX, sm = 0.f;
#pragma unroll 4
    for (int j = 0; j < k; j++) {
        float v = base[(size_t)j * DIM];
        mx = fmaxf(mx, v);
        sm += v;
    }
    float mean = sm / (float)k;
    if (first) {
        d_z[b * 2 * DIM + f]       = mx;
        d_z[b * 2 * DIM + DIM + f] = mean;
    } else {
        d_z[b * 2 * DIM + f]       += mx;
        d_z[b * 2 * DIM + DIM + f] += mean;
    }
}

// ---------------------------------------------------------------------------
// Final MLP: out = relu(z @ lin1^T + b1) @ lin2^T + b2
// ---------------------------------------------------------------------------
__global__ void __launch_bounds__(256) mlp_kernel(
    const float* __restrict__ lin1W, const float* __restrict__ lin1b,
    const float* __restrict__ lin2W, const float* __restrict__ lin2b,
    float* __restrict__ out)
{
    int b = blockIdx.x, t = threadIdx.x;
    int warp = t >> 5, lane = t & 31;
    __shared__ float zsh[2 * DIM];
    __shared__ float y1[DIM];

    for (int i = t; i < 2 * DIM; i += 256) zsh[i] = d_z[b * 2 * DIM + i];
    __syncthreads();

    for (int o = warp * 64; o < warp * 64 + 64; o++) {
        const float* wr = lin1W + (size_t)o * 2 * DIM;
        float s = 0.f;
        for (int j = lane; j < 2 * DIM; j += 32) s = fmaf(zsh[j], wr[j], s);
#pragma unroll
        for (int off = 16; off > 0; off >>= 1) s += __shfl_xor_sync(0xffffffffu, s, off);
        if (lane == 0) y1[o] = fmaxf(s + lin1b[o], 0.f);
    }
    __syncthreads();

    for (int o = warp * 32; o < warp * 32 + 32; o++) {
        const float* wr = lin2W + (size_t)o * DIM;
        float s = 0.f;
        for (int j = lane; j < DIM; j += 32) s = fmaf(y1[j], wr[j], s);
#pragma unroll
        for (int off = 16; off > 0; off >>= 1) s += __shfl_xor_sync(0xffffffffu, s, off);
        if (lane == 0) out[b * 256 + o] = s + lin2b[o];
    }
}

// ---------------------------------------------------------------------------
// Host launcher — kernel launches ONLY (graph-capture safe)
// ---------------------------------------------------------------------------
extern "C" void kernel_launch(void* const* d_in, const int* in_sizes, int n_in,
                              void* d_out, int out_size)
{
    const float* x       = (const float*)d_in[0];
    const int*   ei      = (const int*)  d_in[1];
    const float* c_lin_W = (const float*)d_in[2];
    const float* c_lin_b = (const float*)d_in[3];
    const float* c_upd_W = (const float*)d_in[4];
    const float* pool_w  = (const float*)d_in[5];
    const float* lin1_W  = (const float*)d_in[6];
    const float* lin1_b  = (const float*)d_in[7];
    const float* lin2_W  = (const float*)d_in[8];
    const float* lin2_b  = (const float*)d_in[9];
    float* out = (float*)d_out;

    const int ns[3] = {1024, 820, 656};
    const int ks[3] = {820, 656, 525};

    init_edges_kernel<<<dim3(EMAX / 256, BATCH), 256>>>(ei);
    norms_kernel<<<3, 256>>>(pool_w);

    // pre-split x and weights into fp16 hi/lo planes
    {
        int nx = BATCH * NMAX * DIM / 4;
        split_kernel<<<(nx + 255) / 256, 256>>>(x, 0, nx);
        int nl = 3 * DIM * DIM / 4;
        split_kernel<<<(nl + 255) / 256, 256>>>(c_lin_W, 1, nl);
        int nu = 3 * DIM * 2 * DIM / 4;
        split_kernel<<<(nu + 255) / 256, 256>>>(c_upd_W, 2, nu);
    }

    for (int l = 0; l < 3; l++) {
        int n = ns[l], k = ks[l];
        int inSel = l & 1;
        int outSel = inSel ^ 1;
        int xsel = (l == 0) ? 0 : 1;
        int nrow = (n + 127) / 128;

        // h = relu(x @ Wl^T + bl)
        gemm_h3_kernel<<<dim3(DIM / 128, nrow, BATCH), 256>>>(
            xsel, l, c_lin_b + l * DIM, n);

        build_csr_kernel<<<BATCH, 1024>>>(inSel);

        agg_cat_kernel<<<dim3(n, BATCH), 128>>>(xsel, n);

        // x_new = relu([agg|x] @ Wu^T)
        gemm_h3_kernel<<<dim3(DIM / 128, nrow, BATCH), 256>>>(
            2, l, nullptr, n);

        score_kernel<<<dim3((n + 7) / 8, BATCH), 256>>>(pool_w, l, n);
        topk_kernel<<<BATCH, 512>>>(n, k);
        gather_kernel<<<dim3(k, BATCH), 128>>>(k);
        if (l < 2)
            remap_kernel<<<dim3(EMAX / 256, BATCH), 256>>>(inSel, outSel);

        readout_kernel<<<dim3(DIM / 256, BATCH), 256>>>(k, l == 0 ? 1 : 0);
    }

    mlp_kernel<<<BATCH, 256>>>(lin1_W, lin1_b, lin2_W, lin2_b, out);
}